// round 17
// baseline (speedup 1.0000x reference)
#include <cuda_runtime.h>
#include <cuda_fp16.h>
#include <cstdint>

#define N_USERS 100000
#define N_ITEMS 50000
#define N_NODESC 150000
#define NNZC 2400000
#define DIM 64
#define BATCHC 4096
#define HALFC 4800000u
#define NPAIR 75000
#define EPSC 0.1f
#define INV_TEMP 5.0f

// ---------------- static device scratch (allocation-free) ----------------
__device__ unsigned g_inh[N_NODESC * 32]; // fp16-staged inputs: half2(col 2l,2l+1)
__device__ unsigned g_a1 [N_NODESC * 32]; // e1 half2 (gather-hot, 4B)
__device__ uint2    g_b1 [N_NODESC * 32]; // d1 half4 (gather-hot, 8B)
__device__ float2   g_e1f[N_NODESC * 32]; // e1 fp32 (direct row reads only)
__device__ unsigned g_a2 [N_NODESC * 32]; // e2 half2
__device__ uint2    g_b2 [N_NODESC * 32]; // d2 half4
__device__ float2   g_e2f[N_NODESC * 32]; // e2 fp32 (BPR gather + direct reads)
__device__ int2   g_cv[NNZC];
__device__ int    g_rowptr[N_NODESC + 1];
__device__ int    g_cursor[N_NODESC];
__device__ int    g_counts[N_NODESC];
__device__ int    g_blocksums[256];
__device__ int    g_flags[N_NODESC];
__device__ int    g_uidx[BATCHC];
__device__ int    g_iidx[BATCHC];
__device__ int    g_ucnt;
__device__ int    g_icnt;
__device__ unsigned g_Vh[4][BATCHC * 32]; // half2-packed normalized views
__device__ float  g_posU[BATCHC], g_posI[BATCHC];
__device__ float  g_S[2 * BATCHC];
__device__ float  g_acc[8];               // 0 rec, 1 ssu, 2 ssp

// ---------------- half pack/unpack ----------------
__device__ __forceinline__ uint2 pack4h(float a, float b, float c, float d) {
    __half2 lo = __floats2half2_rn(a, b);
    __half2 hi = __floats2half2_rn(c, d);
    uint2 r;
    r.x = *(const unsigned*)&lo;
    r.y = *(const unsigned*)&hi;
    return r;
}
__device__ __forceinline__ float4 unpack4h2(unsigned lo, unsigned hi) {
    float2 l = __half22float2(*(const __half2*)&lo);
    float2 h = __half22float2(*(const __half2*)&hi);
    return make_float4(l.x, l.y, h.x, h.y);
}
__device__ __forceinline__ unsigned pack2h(float a, float b) {
    __half2 h = __floats2half2_rn(a, b);
    return *(const unsigned*)&h;
}
__device__ __forceinline__ float2 unpack2h(unsigned u) {
    return __half22float2(*(const __half2*)&u);
}

// ---------------- threefry-2x32 (exact JAX schedule) ----------------
__host__ __device__ __forceinline__ unsigned rl32(unsigned x, int r) {
    return (x << r) | (x >> (32 - r));
}
__host__ __device__ __forceinline__ void tf2x32(unsigned k0, unsigned k1,
                                                unsigned x0, unsigned x1,
                                                unsigned& o0, unsigned& o1) {
    unsigned k2 = k0 ^ k1 ^ 0x1BD11BDAu;
    x0 += k0; x1 += k1;
#define TFR(r) { x0 += x1; x1 = rl32(x1, r); x1 ^= x0; }
    TFR(13) TFR(15) TFR(26) TFR(6)
    x0 += k1; x1 += k2 + 1u;
    TFR(17) TFR(29) TFR(16) TFR(24)
    x0 += k2; x1 += k0 + 2u;
    TFR(13) TFR(15) TFR(26) TFR(6)
    x0 += k0; x1 += k1 + 3u;
    TFR(17) TFR(29) TFR(16) TFR(24)
    x0 += k1; x1 += k2 + 4u;
    TFR(13) TFR(15) TFR(26) TFR(6)
    x0 += k2; x1 += k0 + 5u;
#undef TFR
    o0 = x0; o1 = x1;
}
__device__ __forceinline__ float u32_to_unit(unsigned b) {
    return __uint_as_float((b >> 9) | 0x3f800000u) - 1.0f;
}
__device__ __forceinline__ float wredsum(float v) {
#pragma unroll
    for (int o = 16; o; o >>= 1) v += __shfl_xor_sync(0xffffffffu, v, o);
    return v;
}
__device__ __forceinline__ float sgn(float x) {
    return (x > 0.f) ? 1.f : ((x < 0.f) ? -1.f : 0.f);
}
// FMA-only exp for x in [-15, 0]
__device__ __forceinline__ float fexp(float x) {
    float t = x * 1.4426950408889634f;
    float fi = floorf(t);
    float f = t - fi;
    float p = 1.5404e-4f;
    p = fmaf(p, f, 1.3333558e-3f);
    p = fmaf(p, f, 9.6181291e-3f);
    p = fmaf(p, f, 5.5504109e-2f);
    p = fmaf(p, f, 2.4022651e-1f);
    p = fmaf(p, f, 6.9314718e-1f);
    p = fmaf(p, f, 1.0f);
    return __int_as_float(((int)fi + 127) << 23) * p;
}

// per-row noise for standalone rows
__device__ __forceinline__ void row_noise(int row, int lane, unsigned k0, unsigned k1,
                                          float& nx, float& ny, float& sc) {
    int half = (row >= NPAIR);
    unsigned base = (unsigned)(half ? row - NPAIR : row) * 64u + (unsigned)(lane * 2);
    unsigned a0, a1, b0, b1;
    tf2x32(k0, k1, base, base + HALFC, a0, a1);
    tf2x32(k0, k1, base + 1u, base + 1u + HALFC, b0, b1);
    nx = u32_to_unit(half ? a1 : a0);
    ny = u32_to_unit(half ? b1 : b0);
    sc = EPSC * rsqrtf(wredsum(nx * nx + ny * ny));
}

// layer-1 gather from fp16-staged inputs: ONE 4B LDG per nnz/lane
__device__ __forceinline__ float2 csr_row_inh(int row, int lane) {
    int s = g_rowptr[row], e = g_rowptr[row + 1];
    float ax = 0.f, ay = 0.f, bx = 0.f, by = 0.f;
    float cx = 0.f, cy = 0.f, dx = 0.f, dy = 0.f;
    int i = s;
    for (; i + 3 < e; i += 4) {
        int2 c0 = g_cv[i], c1 = g_cv[i + 1], c2 = g_cv[i + 2], c3 = g_cv[i + 3];
        unsigned h0 = g_inh[(c0.x << 5) + lane];
        unsigned h1 = g_inh[(c1.x << 5) + lane];
        unsigned h2 = g_inh[(c2.x << 5) + lane];
        unsigned h3 = g_inh[(c3.x << 5) + lane];
        float v0 = __int_as_float(c0.y), v1 = __int_as_float(c1.y);
        float v2 = __int_as_float(c2.y), v3 = __int_as_float(c3.y);
        float2 p0 = unpack2h(h0), p1 = unpack2h(h1), p2 = unpack2h(h2), p3 = unpack2h(h3);
        ax = fmaf(v0, p0.x, ax); ay = fmaf(v0, p0.y, ay);
        bx = fmaf(v1, p1.x, bx); by = fmaf(v1, p1.y, by);
        cx = fmaf(v2, p2.x, cx); cy = fmaf(v2, p2.y, cy);
        dx = fmaf(v3, p3.x, dx); dy = fmaf(v3, p3.y, dy);
    }
    for (; i < e; i++) {
        int2 c0 = g_cv[i];
        float2 p0 = unpack2h(g_inh[(c0.x << 5) + lane]);
        float v0 = __int_as_float(c0.y);
        ax = fmaf(v0, p0.x, ax); ay = fmaf(v0, p0.y, ay);
    }
    return make_float2((ax + bx) + (cx + dx), (ay + by) + (cy + dy));
}

// layer-2: gather a1 (half2 e1) + b1 (half4 d1): 12 B per nnz/lane
__device__ __forceinline__ void csr_row_l2(int row, int lane, float2& se, float4& sd) {
    int s = g_rowptr[row], e = g_rowptr[row + 1];
    float ex0 = 0.f, ey0 = 0.f, ex1 = 0.f, ey1 = 0.f;
    float dx0 = 0.f, dy0 = 0.f, dz0 = 0.f, dw0 = 0.f;
    float dx1 = 0.f, dy1 = 0.f, dz1 = 0.f, dw1 = 0.f;
    int i = s;
    for (; i + 3 < e; i += 4) {
        int2 c0 = g_cv[i], c1 = g_cv[i + 1], c2 = g_cv[i + 2], c3 = g_cv[i + 3];
        int i0 = (c0.x << 5) + lane, i1 = (c1.x << 5) + lane;
        int i2 = (c2.x << 5) + lane, i3 = (c3.x << 5) + lane;
        unsigned h0 = g_a1[i0], h1 = g_a1[i1], h2 = g_a1[i2], h3 = g_a1[i3];
        uint2 u0 = g_b1[i0], u1 = g_b1[i1], u2 = g_b1[i2], u3 = g_b1[i3];
        float v0 = __int_as_float(c0.y), v1 = __int_as_float(c1.y);
        float v2 = __int_as_float(c2.y), v3 = __int_as_float(c3.y);
        float2 q0 = unpack2h(h0), q1 = unpack2h(h1), q2 = unpack2h(h2), q3 = unpack2h(h3);
        float4 p0 = unpack4h2(u0.x, u0.y), p1 = unpack4h2(u1.x, u1.y);
        float4 p2 = unpack4h2(u2.x, u2.y), p3 = unpack4h2(u3.x, u3.y);
        ex0 = fmaf(v0, q0.x, ex0); ey0 = fmaf(v0, q0.y, ey0);
        ex1 = fmaf(v1, q1.x, ex1); ey1 = fmaf(v1, q1.y, ey1);
        ex0 = fmaf(v2, q2.x, ex0); ey0 = fmaf(v2, q2.y, ey0);
        ex1 = fmaf(v3, q3.x, ex1); ey1 = fmaf(v3, q3.y, ey1);
        dx0 = fmaf(v0, p0.x, dx0); dy0 = fmaf(v0, p0.y, dy0);
        dz0 = fmaf(v0, p0.z, dz0); dw0 = fmaf(v0, p0.w, dw0);
        dx1 = fmaf(v1, p1.x, dx1); dy1 = fmaf(v1, p1.y, dy1);
        dz1 = fmaf(v1, p1.z, dz1); dw1 = fmaf(v1, p1.w, dw1);
        dx0 = fmaf(v2, p2.x, dx0); dy0 = fmaf(v2, p2.y, dy0);
        dz0 = fmaf(v2, p2.z, dz0); dw0 = fmaf(v2, p2.w, dw0);
        dx1 = fmaf(v3, p3.x, dx1); dy1 = fmaf(v3, p3.y, dy1);
        dz1 = fmaf(v3, p3.z, dz1); dw1 = fmaf(v3, p3.w, dw1);
    }
    for (; i < e; i++) {
        int2 c0 = g_cv[i];
        int i0 = (c0.x << 5) + lane;
        float2 q0 = unpack2h(g_a1[i0]);
        uint2 u0 = g_b1[i0];
        float4 p0 = unpack4h2(u0.x, u0.y);
        float v0 = __int_as_float(c0.y);
        ex0 = fmaf(v0, q0.x, ex0); ey0 = fmaf(v0, q0.y, ey0);
        dx0 = fmaf(v0, p0.x, dx0); dy0 = fmaf(v0, p0.y, dy0);
        dz0 = fmaf(v0, p0.z, dz0); dw0 = fmaf(v0, p0.w, dw0);
    }
    se = make_float2(ex0 + ex1, ey0 + ey1);
    sd = make_float4(dx0 + dx1, dy0 + dy1, dz0 + dz1, dw0 + dw1);
}

// BPR layer-3: gather fp32 e2 (accuracy-critical rec path)
__device__ __forceinline__ float2 csr_row_e2(int row, int lane) {
    int s = g_rowptr[row], e = g_rowptr[row + 1];
    float ax = 0.f, ay = 0.f, bx = 0.f, by = 0.f;
    float cx = 0.f, cy = 0.f, dx = 0.f, dy = 0.f;
    int i = s;
    for (; i + 3 < e; i += 4) {
        int2 c0 = g_cv[i], c1 = g_cv[i + 1], c2 = g_cv[i + 2], c3 = g_cv[i + 3];
        float2 q0 = g_e2f[(c0.x << 5) + lane];
        float2 q1 = g_e2f[(c1.x << 5) + lane];
        float2 q2 = g_e2f[(c2.x << 5) + lane];
        float2 q3 = g_e2f[(c3.x << 5) + lane];
        float v0 = __int_as_float(c0.y), v1 = __int_as_float(c1.y);
        float v2 = __int_as_float(c2.y), v3 = __int_as_float(c3.y);
        ax = fmaf(v0, q0.x, ax); ay = fmaf(v0, q0.y, ay);
        bx = fmaf(v1, q1.x, bx); by = fmaf(v1, q1.y, by);
        cx = fmaf(v2, q2.x, cx); cy = fmaf(v2, q2.y, cy);
        dx = fmaf(v3, q3.x, dx); dy = fmaf(v3, q3.y, dy);
    }
    for (; i < e; i++) {
        int2 c0 = g_cv[i];
        float2 q0 = g_e2f[(c0.x << 5) + lane];
        float v0 = __int_as_float(c0.y);
        ax = fmaf(v0, q0.x, ax); ay = fmaf(v0, q0.y, ay);
    }
    return make_float2((ax + bx) + (cx + dx), (ay + by) + (cy + dy));
}

// layer-3 view gather: A*(e2 + d2), half sources: 12 B per nnz/lane
__device__ __forceinline__ float4 csr_row_l3(int row, int lane) {
    int s = g_rowptr[row], e = g_rowptr[row + 1];
    float ax = 0.f, ay = 0.f, az = 0.f, aw = 0.f;
    float bx = 0.f, by = 0.f, bz = 0.f, bw = 0.f;
    int i = s;
    for (; i + 1 < e; i += 2) {
        int2 c0 = g_cv[i], c1 = g_cv[i + 1];
        int i0 = (c0.x << 5) + lane, i1 = (c1.x << 5) + lane;
        float2 e0 = unpack2h(g_a2[i0]);
        float2 e1 = unpack2h(g_a2[i1]);
        uint2 u0 = g_b2[i0], u1 = g_b2[i1];
        float4 p0 = unpack4h2(u0.x, u0.y);
        float4 p1 = unpack4h2(u1.x, u1.y);
        float v0 = __int_as_float(c0.y), v1 = __int_as_float(c1.y);
        ax = fmaf(v0, e0.x + p0.x, ax); ay = fmaf(v0, e0.y + p0.y, ay);
        az = fmaf(v0, e0.x + p0.z, az); aw = fmaf(v0, e0.y + p0.w, aw);
        bx = fmaf(v1, e1.x + p1.x, bx); by = fmaf(v1, e1.y + p1.y, by);
        bz = fmaf(v1, e1.x + p1.z, bz); bw = fmaf(v1, e1.y + p1.w, bw);
    }
    if (i < e) {
        int2 c0 = g_cv[i];
        int i0 = (c0.x << 5) + lane;
        float2 e0 = unpack2h(g_a2[i0]);
        uint2 u0 = g_b2[i0];
        float4 p0 = unpack4h2(u0.x, u0.y);
        float v0 = __int_as_float(c0.y);
        ax = fmaf(v0, e0.x + p0.x, ax); ay = fmaf(v0, e0.y + p0.y, ay);
        az = fmaf(v0, e0.x + p0.z, az); aw = fmaf(v0, e0.y + p0.w, aw);
    }
    return make_float4(ax + bx, ay + by, az + bz, aw + bw);
}

// ---------------- setup (also stages inputs to fp16) ----------------
__global__ void k_init(const float* __restrict__ ue, const float* __restrict__ ie) {
    int i = blockIdx.x * blockDim.x + threadIdx.x;
    if (i < N_NODESC * 32) {
        int row = i >> 5, lane = i & 31;
        float2 v = (row < N_USERS)
            ? ((const float2*)(ue + (row << 6)))[lane]
            : ((const float2*)(ie + ((row - N_USERS) << 6)))[lane];
        g_inh[i] = pack2h(v.x, v.y);
    }
    if (i < N_NODESC) { g_flags[i] = 0; g_counts[i] = 0; }
    if (i < 2 * BATCHC) g_S[i] = 0.f;
    if (i < 8) g_acc[i] = 0.f;
    if (i == 0) { g_ucnt = 0; g_icnt = 0; }
}
__global__ void k_hist(const int* __restrict__ rows) {
    int i = blockIdx.x * blockDim.x + threadIdx.x;
    if (i < NNZC) atomicAdd(&g_counts[rows[i]], 1);
}
__global__ void k_scan1() {
    __shared__ int sh[1024];
    int g = blockIdx.x * 1024 + threadIdx.x;
    int v = (g < N_NODESC) ? g_counts[g] : 0;
    sh[threadIdx.x] = v;
    __syncthreads();
    for (int off = 1; off < 1024; off <<= 1) {
        int t = (threadIdx.x >= off) ? sh[threadIdx.x - off] : 0;
        __syncthreads();
        sh[threadIdx.x] += t;
        __syncthreads();
    }
    if (g < N_NODESC) g_rowptr[g] = sh[threadIdx.x] - v;
    if (threadIdx.x == 1023) g_blocksums[blockIdx.x] = sh[1023];
}
__global__ void k_scan2(int nblocks) {
    __shared__ int sh[256];
    int t = threadIdx.x;
    int v = (t < nblocks) ? g_blocksums[t] : 0;
    sh[t] = v;
    __syncthreads();
    for (int off = 1; off < 256; off <<= 1) {
        int p = (t >= off) ? sh[t - off] : 0;
        __syncthreads();
        sh[t] += p;
        __syncthreads();
    }
    if (t < nblocks) g_blocksums[t] = sh[t] - v;
    if (t == nblocks - 1) g_rowptr[N_NODESC] = sh[t];
}
__global__ void k_scan3() {
    int g = blockIdx.x * blockDim.x + threadIdx.x;
    if (g < N_NODESC) {
        int v = g_rowptr[g] + g_blocksums[g >> 10];
        g_rowptr[g] = v;
        g_cursor[g] = v;
    }
}
__global__ void k_fill(const int* __restrict__ rows, const int* __restrict__ cols,
                       const float* __restrict__ vals) {
    int i = blockIdx.x * blockDim.x + threadIdx.x;
    if (i < NNZC) {
        int p = atomicAdd(&g_cursor[rows[i]], 1);
        g_cv[p] = make_int2(cols[i], __float_as_int(vals[i]));
    }
}

// ---------------- layer 1 ----------------
__global__ void __launch_bounds__(256) k_spmm_e1_noise(unsigned f10, unsigned f11,
                                                       unsigned f20, unsigned f21) {
    int warp = threadIdx.x >> 5;
    int lane = threadIdx.x & 31;
    int sub = warp & 3;
    int hi = warp >> 2;
    int pr = blockIdx.x * 4 + sub;
    int row = pr + hi * NPAIR;
    __shared__ unsigned shn[2][4][32][2];
    float2 ea = csr_row_inh(row, lane);
    unsigned myx[2], myy[2];
    if (!hi) {
        unsigned base = (unsigned)pr * 64u + (unsigned)(lane * 2);
#pragma unroll
        for (int vv = 0; vv < 2; vv++) {
            unsigned k0 = vv ? f20 : f10, k1 = vv ? f21 : f11;
            unsigned a0, a1, b0, b1;
            tf2x32(k0, k1, base, base + HALFC, a0, a1);
            tf2x32(k0, k1, base + 1u, base + 1u + HALFC, b0, b1);
            myx[vv] = a0; myy[vv] = b0;
            shn[vv][sub][lane][0] = a1;
            shn[vv][sub][lane][1] = b1;
        }
    }
    __syncthreads();
    if (hi) {
#pragma unroll
        for (int vv = 0; vv < 2; vv++) {
            myx[vv] = shn[vv][sub][lane][0];
            myy[vv] = shn[vv][sub][lane][1];
        }
    }
    float o1x, o1y, o2x, o2y;
    {
        float nx = u32_to_unit(myx[0]), ny = u32_to_unit(myy[0]);
        float sc = EPSC * rsqrtf(wredsum(nx * nx + ny * ny));
        o1x = sgn(ea.x) * nx * sc;
        o1y = sgn(ea.y) * ny * sc;
    }
    {
        float nx = u32_to_unit(myx[1]), ny = u32_to_unit(myy[1]);
        float sc = EPSC * rsqrtf(wredsum(nx * nx + ny * ny));
        o2x = sgn(ea.x) * nx * sc;
        o2y = sgn(ea.y) * ny * sc;
    }
    int idx = (row << 5) + lane;
    g_e1f[idx] = ea;
    g_a1[idx] = pack2h(ea.x, ea.y);
    g_b1[idx] = pack4h(o1x, o1y, o2x, o2y);
}

// ---------------- layer 2 ----------------
__global__ void __launch_bounds__(256) k_spmm_l2(unsigned f10, unsigned f11,
                                                 unsigned f20, unsigned f21) {
    int warp = threadIdx.x >> 5;
    int lane = threadIdx.x & 31;
    int sub = warp & 3;
    int hi = warp >> 2;
    int pr = blockIdx.x * 4 + sub;
    int row = pr + hi * NPAIR;
    __shared__ unsigned shn[2][4][32][2];
    float2 se;
    float4 sd;
    csr_row_l2(row, lane, se, sd);
    unsigned myx[2], myy[2];
    if (!hi) {
        unsigned base = (unsigned)pr * 64u + (unsigned)(lane * 2);
#pragma unroll
        for (int vv = 0; vv < 2; vv++) {
            unsigned k0 = vv ? f20 : f10, k1 = vv ? f21 : f11;
            unsigned a0, a1, b0, b1;
            tf2x32(k0, k1, base, base + HALFC, a0, a1);
            tf2x32(k0, k1, base + 1u, base + 1u + HALFC, b0, b1);
            myx[vv] = a0; myy[vv] = b0;
            shn[vv][sub][lane][0] = a1;
            shn[vv][sub][lane][1] = b1;
        }
    }
    __syncthreads();
    if (hi) {
#pragma unroll
        for (int vv = 0; vv < 2; vv++) {
            myx[vv] = shn[vv][sub][lane][0];
            myy[vv] = shn[vv][sub][lane][1];
        }
    }
    float y1x = se.x + sd.x, y1y = se.y + sd.y;
    float y2x = se.x + sd.z, y2y = se.y + sd.w;
    {
        float nx = u32_to_unit(myx[0]), ny = u32_to_unit(myy[0]);
        float sc = EPSC * rsqrtf(wredsum(nx * nx + ny * ny));
        sd.x += sgn(y1x) * nx * sc;
        sd.y += sgn(y1y) * ny * sc;
    }
    {
        float nx = u32_to_unit(myx[1]), ny = u32_to_unit(myy[1]);
        float sc = EPSC * rsqrtf(wredsum(nx * nx + ny * ny));
        sd.z += sgn(y2x) * nx * sc;
        sd.w += sgn(y2y) * ny * sc;
    }
    int idx = (row << 5) + lane;
    g_e2f[idx] = se;
    g_a2[idx] = pack2h(se.x, se.y);
    g_b2[idx] = pack4h(sd.x, sd.y, sd.z, sd.w);
}

// ---------------- order-free unique ----------------
__global__ void k_unique2(const int* __restrict__ ul, const int* __restrict__ pl) {
    int i = blockIdx.x * blockDim.x + threadIdx.x;
    if (i >= 2 * BATCHC) return;
    int which = (i >= BATCHC);
    int j = which ? i - BATCHC : i;
    int v = which ? pl[j] : ul[j];
    int fidx = which ? (N_USERS + v) : v;
    if (atomicExch(&g_flags[fidx], 1) == 0) {
        int p = atomicAdd(which ? &g_icnt : &g_ucnt, 1);
        (which ? g_iidx : g_uidx)[p] = v;
    }
}

// ---------------- merged BPR + view-finalize ----------------
__global__ void __launch_bounds__(256) k_bprvf(const int* __restrict__ ul,
                                               const int* __restrict__ pl,
                                               const int* __restrict__ nl,
                                               unsigned f10, unsigned f11,
                                               unsigned f20, unsigned f21) {
    int w = (blockIdx.x * blockDim.x + threadIdx.x) >> 5;
    int lane = threadIdx.x & 31;
    if (w < BATCHC) {
        const float third = 1.f / 3.f;
        int ru = ul[w];
        int rp = N_USERS + pl[w];
        int rn = N_USERS + nl[w];
        float2 u3 = csr_row_e2(ru, lane);
        float2 p3 = csr_row_e2(rp, lane);
        float2 n3 = csr_row_e2(rn, lane);
        float2 u1 = g_e1f[(ru << 5) + lane], u2 = g_e2f[(ru << 5) + lane];
        float2 p1 = g_e1f[(rp << 5) + lane], p2 = g_e2f[(rp << 5) + lane];
        float2 n1 = g_e1f[(rn << 5) + lane], n2 = g_e2f[(rn << 5) + lane];
        float ux = (u1.x + u2.x + u3.x) * third, uy = (u1.y + u2.y + u3.y) * third;
        float px = (p1.x + p2.x + p3.x) * third, py = (p1.y + p2.y + p3.y) * third;
        float nx = (n1.x + n2.x + n3.x) * third, ny = (n1.y + n2.y + n3.y) * third;
        float pos = wredsum(ux * px + uy * py);
        float neg = wredsum(ux * nx + uy * ny);
        float ssu = wredsum(ux * ux + uy * uy);
        float ssp = wredsum(px * px + py * py);
        if (lane == 0) {
            float d = pos - neg;
            float sig = 1.f / (1.f + expf(-d));
            atomicAdd(&g_acc[0], -logf(1e-7f + sig));
            atomicAdd(&g_acc[1], ssu);
            atomicAdd(&g_acc[2], ssp);
        }
        return;
    }
    int wv = w - BATCHC;
    int isItem = (wv >= BATCHC);
    int j = isItem ? wv - BATCHC : wv;
    int cnt = isItem ? g_icnt : g_ucnt;
    if (j >= cnt) return;
    int row = isItem ? (N_USERS + g_iidx[j]) : g_uidx[j];
    float4 a3 = csr_row_l3(row, lane);
    float nx, ny, sc;
    row_noise(row, lane, f10, f11, nx, ny, sc);
    a3.x += sgn(a3.x) * nx * sc;
    a3.y += sgn(a3.y) * ny * sc;
    row_noise(row, lane, f20, f21, nx, ny, sc);
    a3.z += sgn(a3.z) * nx * sc;
    a3.w += sgn(a3.w) * ny * sc;
    int idx = (row << 5) + lane;
    float2 e1r = g_e1f[idx];
    float2 e2r = g_e2f[idx];
    uint2 b1r = g_b1[idx];
    uint2 b2r = g_b2[idx];
    float4 d1r = unpack4h2(b1r.x, b1r.y);
    float4 d2r = unpack4h2(b2r.x, b2r.y);
    float s1x = (e1r.x + d1r.x) + (e2r.x + d2r.x) + a3.x;
    float s1y = (e1r.y + d1r.y) + (e2r.y + d2r.y) + a3.y;
    float inv1 = rsqrtf(wredsum(s1x * s1x + s1y * s1y));
    s1x *= inv1; s1y *= inv1;
    float s2x = (e1r.x + d1r.z) + (e2r.x + d2r.z) + a3.z;
    float s2y = (e1r.y + d1r.w) + (e2r.y + d2r.w) + a3.w;
    float inv2 = rsqrtf(wredsum(s2x * s2x + s2y * s2y));
    s2x *= inv2; s2y *= inv2;
    g_Vh[0 * 2 + isItem][(j << 5) + lane] = pack2h(s1x, s1y);
    g_Vh[1 * 2 + isItem][(j << 5) + lane] = pack2h(s2x, s2y);
    float d = wredsum(s2x * s1x + s2y * s1y);
    if (lane == 0) (isItem ? g_posI : g_posU)[j] = d * INV_TEMP;
}

// ---------------- InfoNCE via mma.sync (HMMA): warp = m16 x n32 tile ----------------
__global__ void __launch_bounds__(256) k_nce() {
    int which = blockIdx.z;
    const unsigned* __restrict__ V1 = g_Vh[0 * 2 + which];
    const unsigned* __restrict__ V2 = g_Vh[1 * 2 + which];
    float* __restrict__ S = g_S + which * BATCHC;
    int U = which ? g_icnt : g_ucnt;
    int warp = threadIdx.x >> 5;
    int lane = threadIdx.x & 31;
    int rb = blockIdx.y * 128 + warp * 16;
    int cb = blockIdx.x * 32;
    if (rb >= U || cb >= U) return;
    int l4 = lane >> 2, lm = lane & 3;
    unsigned a0[8], a1[8];
    {
        const unsigned* A0 = V1 + ((rb + l4) << 5) + lm;
        const unsigned* A1 = V1 + ((rb + l4 + 8) << 5) + lm;
#pragma unroll
        for (int t = 0; t < 8; t++) { a0[t] = A0[4 * t]; a1[t] = A1[4 * t]; }
    }
    float ssum0 = 0.f, ssum1 = 0.f;
#pragma unroll
    for (int nt = 0; nt < 4; nt++) {
        int col0 = cb + nt * 8;
        unsigned b[8];
        const unsigned* B0 = V2 + ((col0 + l4) << 5) + lm;
#pragma unroll
        for (int t = 0; t < 8; t++) b[t] = B0[4 * t];
        float c0 = 0.f, c1 = 0.f, c2 = 0.f, c3 = 0.f;
#pragma unroll
        for (int kb = 0; kb < 4; kb++) {
            asm volatile(
                "mma.sync.aligned.m16n8k16.row.col.f32.f16.f16.f32 "
                "{%0,%1,%2,%3}, {%4,%5,%6,%7}, {%8,%9}, {%0,%1,%2,%3};"
                : "+f"(c0), "+f"(c1), "+f"(c2), "+f"(c3)
                : "r"(a0[2 * kb]), "r"(a1[2 * kb]),
                  "r"(a0[2 * kb + 1]), "r"(a1[2 * kb + 1]),
                  "r"(b[2 * kb]), "r"(b[2 * kb + 1]));
        }
        int cA = col0 + lm * 2, cB = cA + 1;
        if (cA < U) { ssum0 += fexp(fmaf(c0, INV_TEMP, -5.0f));
                      ssum1 += fexp(fmaf(c2, INV_TEMP, -5.0f)); }
        if (cB < U) { ssum0 += fexp(fmaf(c1, INV_TEMP, -5.0f));
                      ssum1 += fexp(fmaf(c3, INV_TEMP, -5.0f)); }
    }
#pragma unroll
    for (int o = 1; o < 4; o <<= 1) {
        ssum0 += __shfl_xor_sync(0xffffffffu, ssum0, o);
        ssum1 += __shfl_xor_sync(0xffffffffu, ssum1, o);
    }
    if (lm == 0) {
        if (rb + l4 < U)     atomicAdd(&S[rb + l4], ssum0);
        if (rb + l4 + 8 < U) atomicAdd(&S[rb + l4 + 8], ssum1);
    }
}

// ---------------- NCE finalize + output ----------------
__global__ void __launch_bounds__(256) k_final(float* out) {
    int tid = threadIdx.x;
    int lane = tid & 31, warp = tid >> 5;
    float cU = 0.f, cI = 0.f;
    int Uu = g_ucnt, Ui = g_icnt;
    for (int i = tid; i < 2 * BATCHC; i += 256) {
        int which = (i >= BATCHC);
        int j = i - which * BATCHC;
        int U = which ? Ui : Uu;
        if (j < U) {
            float c = 5.0f + logf(g_S[i]) - (which ? g_posI[j] : g_posU[j]);
            if (which) cI += c; else cU += c;
        }
    }
    cU = wredsum(cU);
    cI = wredsum(cI);
    __shared__ float sU[8], sI[8];
    if (lane == 0) { sU[warp] = cU; sI[warp] = cI; }
    __syncthreads();
    if (tid == 0) {
        float tU = 0.f, tI = 0.f;
        for (int w = 0; w < 8; w++) { tU += sU[w]; tI += sI[w]; }
        float rec = g_acc[0] / (float)BATCHC;
        float reg = 1e-4f * (sqrtf(g_acc[1]) + sqrtf(g_acc[2]));
        float cl = 0.2f * (tU / (float)Uu + tI / (float)Ui);
        out[0] = rec + reg + cl;
        out[1] = cl;
    }
}

// ---------------- launch ----------------
extern "C" void kernel_launch(void* const* d_in, const int* in_sizes, int n_in,
                              void* d_out, int out_size) {
    const float* ue = (const float*)d_in[0];
    const float* ie = (const float*)d_in[1];
    const float* av = (const float*)d_in[2];
    const int*   ar = (const int*)d_in[3];
    const int*   ac = (const int*)d_in[4];
    const int*   ul = (const int*)d_in[5];
    const int*   pl = (const int*)d_in[6];
    const int*   nl = (const int*)d_in[7];
    float* out = (float*)d_out;

    const int SCAN_BLOCKS = (N_NODESC + 1023) / 1024;
    const int PAIRED_BLOCKS = NPAIR / 4;

    unsigned seeds[2] = {101u, 202u};
    unsigned fk[2][3][2];
    for (int vv = 0; vv < 2; vv++)
        for (int k = 0; k < 3; k++)
            tf2x32(0u, seeds[vv], 0u, (unsigned)k, fk[vv][k][0], fk[vv][k][1]);

    k_init<<<(N_NODESC * 32 + 255) / 256, 256>>>(ue, ie);
    k_hist<<<(NNZC + 255) / 256, 256>>>(ar);
    k_scan1<<<SCAN_BLOCKS, 1024>>>();
    k_scan2<<<1, 256>>>(SCAN_BLOCKS);
    k_scan3<<<SCAN_BLOCKS, 1024>>>();
    k_fill<<<(NNZC + 255) / 256, 256>>>(ar, ac, av);
    k_unique2<<<(2 * BATCHC + 255) / 256, 256>>>(ul, pl);

    k_spmm_e1_noise<<<PAIRED_BLOCKS, 256>>>(
        fk[0][0][0], fk[0][0][1], fk[1][0][0], fk[1][0][1]);
    k_spmm_l2<<<PAIRED_BLOCKS, 256>>>(fk[0][1][0], fk[0][1][1], fk[1][1][0], fk[1][1][1]);
    k_bprvf<<<(3 * BATCHC * 32) / 256, 256>>>(ul, pl, nl,
        fk[0][2][0], fk[0][2][1], fk[1][2][0], fk[1][2][1]);

    dim3 nce_grid(BATCHC / 32, BATCHC / 128, 2);
    k_nce<<<nce_grid, 256>>>();
    k_final<<<1, 256>>>(out);
}